// round 4
// baseline (speedup 1.0000x reference)
#include <cuda_runtime.h>
#include <cuda_bf16.h>

#define FULLM 0xFFFFFFFFu

constexpr int B_ = 8;
constexpr int N_ = 2048;
constexpr int K_ = 32;
constexpr int CO_ = 64;

// ---------------- static scratch (no allocation) ----------------
__device__ float d_sq[B_ * N_];
__device__ int   d_idx[B_ * N_ * K_];
__device__ float d_h [B_ * N_ * CO_];
__device__ float d_mx[B_ * N_ * CO_];
__device__ float d_mn[B_ * N_ * CO_];
__device__ float d_sum[CO_];
__device__ float d_ssq[CO_];
__device__ float d_scale[CO_];
__device__ float d_shift[CO_];

// ---------------- helpers ----------------
__device__ __forceinline__ void warp_argmax(float v, int lane, float& mval, int& mlane) {
    int vl = lane;
#pragma unroll
    for (int off = 16; off > 0; off >>= 1) {
        float ov = __shfl_down_sync(FULLM, v, off);
        int   ol = __shfl_down_sync(FULLM, vl, off);
        if (ov > v) { v = ov; vl = ol; }
    }
    mval  = __shfl_sync(FULLM, v, 0);
    mlane = __shfl_sync(FULLM, vl, 0);
}

// ---------------- squared norms ----------------
template<int C>
__global__ void sqnorm_kernel(const float* __restrict__ xin) {
    const float* x = xin ? xin : (const float*)d_h;
    int i = blockIdx.x * blockDim.x + threadIdx.x;
    if (i >= B_ * N_) return;
    const float* p = x + (size_t)i * C;
    float s = 0.f;
    if (C == 3) {
        s = p[0]*p[0] + p[1]*p[1] + p[2]*p[2];
    } else {
#pragma unroll
        for (int c4 = 0; c4 < C / 4; c4++) {
            float4 f = reinterpret_cast<const float4*>(p)[c4];
            s += f.x*f.x + f.y*f.y + f.z*f.z + f.w*f.w;
        }
    }
    d_sq[i] = s;
}

// ---------------- kNN: 32 query rows / block, 64-col tiles, online top-32 ----------------
template<int C>
__global__ void __launch_bounds__(256) knn_kernel(const float* __restrict__ xin) {
    const float* x = xin ? xin : (const float*)d_h;
    __shared__ float AT[C][36];   // [channel][query row]
    __shared__ float BT[C][68];   // [channel][candidate col]
    __shared__ float sqa[32];
    __shared__ float sqb[64];

    const int b    = blockIdx.y;
    const int row0 = blockIdx.x * 32;
    const int tid  = threadIdx.x;
    const int w    = tid >> 5, l = tid & 31;
    const float* xb = x + (size_t)b * N_ * C;

    if (C == 3) {
        for (int v = tid; v < 96; v += 256) {
            int c = v >> 5, p = v & 31;
            AT[c][p] = xb[(size_t)(row0 + p) * 3 + c];
        }
    } else {
        for (int v = tid; v < 32 * (C / 4); v += 256) {
            int c4 = v >> 5, p = v & 31;
            float4 f = *reinterpret_cast<const float4*>(xb + (size_t)(row0 + p) * C + 4 * c4);
            AT[4*c4+0][p] = f.x; AT[4*c4+1][p] = f.y;
            AT[4*c4+2][p] = f.z; AT[4*c4+3][p] = f.w;
        }
    }
    if (tid < 32) sqa[tid] = d_sq[b * N_ + row0 + tid];

    // warp w owns rows 4w..4w+3; each lane holds one of the 32 current-best slots
    float val[4], cmax[4];
    int   vidx[4], cml[4];
#pragma unroll
    for (int q = 0; q < 4; q++) { val[q] = 3.4e38f; vidx[q] = 0; cmax[q] = 3.4e38f; cml[q] = 0; }

    for (int tile = 0; tile < N_ / 64; tile++) {
        const int col0 = tile * 64;
        __syncthreads();
        if (C == 3) {
            for (int v = tid; v < 192; v += 256) {
                int c = v >> 6, p = v & 63;
                BT[c][p] = xb[(size_t)(col0 + p) * 3 + c];
            }
        } else {
            for (int v = tid; v < 64 * (C / 4); v += 256) {
                int c4 = v >> 6, p = v & 63;
                float4 f = *reinterpret_cast<const float4*>(xb + (size_t)(col0 + p) * C + 4 * c4);
                BT[4*c4+0][p] = f.x; BT[4*c4+1][p] = f.y;
                BT[4*c4+2][p] = f.z; BT[4*c4+3][p] = f.w;
            }
        }
        if (tid < 64) sqb[tid] = d_sq[b * N_ + col0 + tid];
        __syncthreads();

        // GEMM micro-tile: rows 4w..4w+3 x cols 2l, 2l+1
        float acc[4][2] = {};
#pragma unroll 8
        for (int c = 0; c < C; c++) {
            float4 av = *reinterpret_cast<const float4*>(&AT[c][4 * w]);
            float2 bv = *reinterpret_cast<const float2*>(&BT[c][2 * l]);
            acc[0][0] += av.x * bv.x; acc[0][1] += av.x * bv.y;
            acc[1][0] += av.y * bv.x; acc[1][1] += av.y * bv.y;
            acc[2][0] += av.z * bv.x; acc[2][1] += av.z * bv.y;
            acc[3][0] += av.w * bv.x; acc[3][1] += av.w * bv.y;
        }

#pragma unroll
        for (int q = 0; q < 4; q++) {
            float sa = sqa[4 * w + q];
#pragma unroll
            for (int ch = 0; ch < 2; ch++) {
                float dc = sa + sqb[2 * l + ch] - 2.f * acc[q][ch];
                int   mc = col0 + 2 * l + ch;
                if (tile == 0 && ch == 0) {
                    val[q] = dc; vidx[q] = mc;
                    warp_argmax(val[q], l, cmax[q], cml[q]);
                    continue;
                }
                unsigned mask = __ballot_sync(FULLM, dc < cmax[q]);
                while (mask) {
                    int s = __ffs(mask) - 1;
                    float dn = __shfl_sync(FULLM, dc, s);
                    int   mn = __shfl_sync(FULLM, mc, s);
                    if (l == cml[q]) { val[q] = dn; vidx[q] = mn; }
                    warp_argmax(val[q], l, cmax[q], cml[q]);
                    mask &= ~(1u << s);
                    mask &= __ballot_sync(FULLM, dc < cmax[q]);
                }
            }
        }
    }
#pragma unroll
    for (int q = 0; q < 4; q++)
        d_idx[((size_t)(b * N_ + row0 + 4 * w + q)) * K_ + l] = vidx[q];
}

// ---------------- stats helpers ----------------
__global__ void zero_stats_kernel() {
    int t = threadIdx.x;
    if (t < CO_) { d_sum[t] = 0.f; d_ssq[t] = 0.f; }
}

__global__ void finalize_kernel(const float* __restrict__ gamma, const float* __restrict__ beta) {
    int o = threadIdx.x;
    if (o < CO_) {
        float cnt  = (float)(B_ * N_ * K_);
        float mean = d_sum[o] / cnt;
        float var  = d_ssq[o] / cnt - mean * mean;
        float sc   = gamma[o] * rsqrtf(var + 1e-5f);
        d_scale[o] = sc;
        d_shift[o] = beta[o] - mean * sc;
    }
}

// ---------------- fused conv: GEMM + per-point sum/ssq/max/min over k ----------------
// block: 256 threads, handles 2 points (64 gathered neighbor rows), all 64 output cols
template<int CIN>
__global__ void __launch_bounds__(256) conv_kernel(const float* __restrict__ xin,
                                                   const float* __restrict__ W) {
    const float* x = xin ? xin : (const float*)d_h;
    __shared__ float swd[CIN][64];   // [c][o] = W[o][c]
    __shared__ float buf[64][65];    // gathered features, then y tile
    __shared__ float bs[2][64];      // per-point center term
    __shared__ float cen[2][CIN];
    __shared__ int   sidx[64];
    __shared__ float cs[64], css[64];

    const int tid = threadIdx.x;
    const int pid = blockIdx.x;
    const int b   = pid >> 10;          // 1024 point-pairs per batch
    const int n0  = (pid & 1023) * 2;
    const size_t base_pt = (size_t)b * N_;

    if (tid < 64) sidx[tid] = d_idx[(base_pt + n0 + (tid >> 5)) * K_ + (tid & 31)];
    for (int v = tid; v < CIN * 64; v += 256) {
        int o = v & 63, c = v >> 6;
        swd[c][o] = W[o * 2 * CIN + c];
    }
    if (tid < 2 * CIN) {
        int p = tid / CIN, c = tid - p * CIN;
        cen[p][c] = x[(base_pt + n0 + p) * CIN + c];
    }
    __syncthreads();

    // gather neighbor features
    if constexpr (CIN == 3) {
        for (int v = tid; v < 64; v += 256) {
            const float* src = x + (base_pt + sidx[v]) * 3;
            buf[v][0] = src[0]; buf[v][1] = src[1]; buf[v][2] = src[2];
        }
    } else {
        for (int v = tid; v < 64 * (CIN / 4); v += 256) {
            int r = v >> 4, c4 = v & 15;
            float4 f = *reinterpret_cast<const float4*>(x + (base_pt + sidx[r]) * CIN + 4 * c4);
            buf[r][4*c4+0] = f.x; buf[r][4*c4+1] = f.y;
            buf[r][4*c4+2] = f.z; buf[r][4*c4+3] = f.w;
        }
    }

    // base[p][o] = sum_c cen[p][c] * (W[o][CIN+c] - W[o][c]) : warp per (p,o)
    // NOTE: strided over c so it is correct for CIN > 32.
    {
        int w = tid >> 5, l = tid & 31;
        for (int j = w; j < 128; j += 8) {
            int p = j >> 6, o = j & 63;
            float t = 0.f;
            for (int c = l; c < CIN; c += 32)
                t += cen[p][c] * (W[o * 2 * CIN + CIN + c] - W[o * 2 * CIN + c]);
#pragma unroll
            for (int off = 16; off > 0; off >>= 1) t += __shfl_down_sync(FULLM, t, off);
            if (l == 0) bs[p][o] = t;
        }
    }
    __syncthreads();

    // GEMM: thread -> rows rb, rb+32 x cols 8g..8g+7
    const int g = tid & 7, rb = tid >> 3;
    float acc[2][8] = {};
#pragma unroll 4
    for (int c = 0; c < CIN; c++) {
        float a0 = buf[rb][c];
        float a1 = buf[rb + 32][c];
        float4 b0 = *reinterpret_cast<const float4*>(&swd[c][8 * g]);
        float4 b1 = *reinterpret_cast<const float4*>(&swd[c][8 * g + 4]);
        acc[0][0] += a0 * b0.x; acc[0][1] += a0 * b0.y; acc[0][2] += a0 * b0.z; acc[0][3] += a0 * b0.w;
        acc[0][4] += a0 * b1.x; acc[0][5] += a0 * b1.y; acc[0][6] += a0 * b1.z; acc[0][7] += a0 * b1.w;
        acc[1][0] += a1 * b0.x; acc[1][1] += a1 * b0.y; acc[1][2] += a1 * b0.z; acc[1][3] += a1 * b0.w;
        acc[1][4] += a1 * b1.x; acc[1][5] += a1 * b1.y; acc[1][6] += a1 * b1.z; acc[1][7] += a1 * b1.w;
    }
    __syncthreads();   // all reads of buf done
#pragma unroll
    for (int j = 0; j < 8; j++) {
        buf[rb][8 * g + j]      = acc[0][j];
        buf[rb + 32][8 * g + j] = acc[1][j];
    }
    __syncthreads();

    // reduce over the 32 neighbors of each point
    const int p = tid >> 6, o = tid & 63;
    float sadj = 0.f, ssadj = 0.f;
    if (tid < 128) {
        float s = 0.f, ss = 0.f, mx = -3.4e38f, mn = 3.4e38f;
#pragma unroll 8
        for (int r = 0; r < 32; r++) {
            float v = buf[p * 32 + r][o];
            s += v; ss += v * v;
            mx = fmaxf(mx, v); mn = fminf(mn, v);
        }
        float bb = bs[p][o];
        mx += bb; mn += bb;
        sadj  = s + 32.f * bb;
        ssadj = ss + 2.f * bb * s + 32.f * bb * bb;
        size_t gi = (base_pt + n0 + p) * 64 + o;
        d_mx[gi] = mx;
        d_mn[gi] = mn;
        if (p == 0) { cs[o] = sadj; css[o] = ssadj; }
    }
    __syncthreads();
    if (tid < 128 && p == 1) {
        atomicAdd(&d_sum[o], cs[o] + sadj);
        atomicAdd(&d_ssq[o], css[o] + ssadj);
    }
}

// ---------------- pass B: apply BN affine + LeakyReLU via monotone max/min trick ----------------
__global__ void passb_kernel(float* __restrict__ outp) {
    float* out = outp ? outp : (float*)d_h;
    int e = blockIdx.x * 256 + threadIdx.x;
    if (e >= B_ * N_ * CO_) return;
    int o = e & 63;
    float sc = d_scale[o];
    float v  = (sc >= 0.f) ? d_mx[e] : d_mn[e];
    float y  = sc * v + d_shift[o];
    out[e] = (y >= 0.f) ? y : 0.2f * y;
}

// ---------------- launch ----------------
extern "C" void kernel_launch(void* const* d_in, const int* in_sizes, int n_in,
                              void* d_out, int out_size) {
    const float* a  = (const float*)d_in[0];
    // d_in[1] is k (always 32; compile-time)
    const float* W1 = (const float*)d_in[2];
    const float* g1 = (const float*)d_in[3];
    const float* b1 = (const float*)d_in[4];
    const float* W2 = (const float*)d_in[5];
    const float* g2 = (const float*)d_in[6];
    const float* b2 = (const float*)d_in[7];
    float* out = (float*)d_out;

    dim3 kg(N_ / 32, B_);
    int  pts = B_ * N_;

    // stage 1 (C = 3)
    sqnorm_kernel<3><<<(pts + 255) / 256, 256>>>(a);
    knn_kernel<3><<<kg, 256>>>(a);
    zero_stats_kernel<<<1, 64>>>();
    conv_kernel<3><<<pts / 2, 256>>>(a, W1);
    finalize_kernel<<<1, 64>>>(g1, b1);
    passb_kernel<<<(pts * CO_ + 255) / 256, 256>>>(nullptr);   // -> d_h

    // stage 2 (C = 64)
    sqnorm_kernel<64><<<(pts + 255) / 256, 256>>>(nullptr);
    knn_kernel<64><<<kg, 256>>>(nullptr);
    zero_stats_kernel<<<1, 64>>>();
    conv_kernel<64><<<pts / 2, 256>>>(nullptr, W2);
    finalize_kernel<<<1, 64>>>(g2, b2);
    passb_kernel<<<(pts * CO_ + 255) / 256, 256>>>(out);       // -> d_out
}